// round 8
// baseline (speedup 1.0000x reference)
#include <cuda_runtime.h>

#define LSEQ 32768
#define T 14
#define EMB 300
#define CHUNKS 512
#define CB 64             // chunk length (CHUNKS*CB == LSEQ)
#define SUPER 32          // supernodes per side
#define SCH 16            // chunks per supernode
#define START_TAG 12
#define STOP_TAG 13
#define NEGV (-10000.0f)
#define NINF (-1e30f)

// ---------------- scratch (static device globals; no allocation) -------------
__device__ float g_goldpart[CHUNKS];
__device__ float g_Em[CHUNKS * 224];           // fwd chunk mats (linear, row-norm)
__device__ float g_m[CHUNKS * 16];
__device__ float g_Cv[CHUNKS * 224];           // viterbi chunk mats
__device__ float g_SEm[SUPER * 224];
__device__ float g_Sm[SUPER * 16];
__device__ float g_SCv[SUPER * 224];
__device__ float g_vsuper[SUPER * 16];
__device__ int   g_best_last;
__device__ __align__(16) unsigned char g_F[CHUNKS * T];
__device__ int   g_carry[CHUNKS];
// dataflow counters; all reset by the LAST-done block at end of kernel
__device__ int   g_cntc[2 * SUPER];
__device__ int   g_cnts[2];
__device__ int   g_scanv;
__device__ int   g_cnt_bp;
__device__ int   g_flag;
__device__ int   g_cnt_done;

__device__ __forceinline__ void ld14(const float* p, float* u) {
    const float4* q = (const float4*)p;
    float4 a = q[0], b = q[1], c = q[2], d = q[3];
    u[0]=a.x; u[1]=a.y; u[2]=a.z; u[3]=a.w;
    u[4]=b.x; u[5]=b.y; u[6]=b.z; u[7]=b.w;
    u[8]=c.x; u[9]=c.y; u[10]=c.z; u[11]=c.w;
    u[12]=d.x; u[13]=d.y;
}
__device__ __forceinline__ void ld14cg(const float* p, float* u) {
    const float4* q = (const float4*)p;
    float4 a = __ldcg(q), b = __ldcg(q+1), c = __ldcg(q+2), d = __ldcg(q+3);
    u[0]=a.x; u[1]=a.y; u[2]=a.z; u[3]=a.w;
    u[4]=b.x; u[5]=b.y; u[6]=b.z; u[7]=b.w;
    u[8]=c.x; u[9]=c.y; u[10]=c.z; u[11]=c.w;
    u[12]=d.x; u[13]=d.y;
}
__device__ __forceinline__ float max14(const float* u) {
    float a0=fmaxf(u[0],u[1]), a1=fmaxf(u[2],u[3]), a2=fmaxf(u[4],u[5]);
    float a3=fmaxf(u[6],u[7]), a4=fmaxf(u[8],u[9]), a5=fmaxf(u[10],u[11]);
    float a6=fmaxf(u[12],u[13]);
    float b0=fmaxf(a0,a1), b1=fmaxf(a2,a3), b2=fmaxf(a4,a5);
    return fmaxf(fmaxf(b0,b1), fmaxf(b2,a6));
}
// first-max argmax (ties -> lowest index)
__device__ __forceinline__ void amax14(const float* a, float& best, int& arg) {
    float v[7]; int ix[7];
#pragma unroll
    for (int p = 0; p < 7; p++) {
        bool t = a[2*p] >= a[2*p+1];
        v[p] = t ? a[2*p] : a[2*p+1];
        ix[p] = t ? 2*p : 2*p+1;
    }
    bool t0 = v[0] >= v[1]; float w0 = t0?v[0]:v[1]; int j0 = t0?ix[0]:ix[1];
    bool t1 = v[2] >= v[3]; float w1 = t1?v[2]:v[3]; int j1 = t1?ix[2]:ix[3];
    bool t2 = v[4] >= v[5]; float w2 = t2?v[4]:v[5]; int j2 = t2?ix[4]:ix[5];
    bool s0 = w0 >= w1; float x0 = s0?w0:w1; int y0 = s0?j0:j1;
    bool s1 = w2 >= v[6]; float x1 = s1?w2:v[6]; int y1 = s1?j2:ix[6];
    bool s2 = x0 >= x1; best = s2?x0:x1; arg = s2?y0:y1;
}

// Every vector-accessed member is individually 16B-aligned (misaligned int4 on
// s.Fs was the R6 failure). Byte arrays sit at the end, each alignas(16).
struct SMem {
    alignas(16) float Ws[T * EMB];          // feats phase only
    alignas(16) float raw[CB * 16];         // raw feats (vit + bp)
    alignas(16) float eaux[CB * 16];        // exp(feat - fmax) (fwd)
    alignas(16) float Ucol[2][224];         // per-column double buffer / super Ubuf
    alignas(16) float Trs[224];             // trans staging / super A
    alignas(16) float Msm[224];             // row-norm staging
    alignas(16) float fmaxs[CB];
    alignas(16) float red[256];
    alignas(16) float term_s[16];
    alignas(16) unsigned char bp_s[CB * T];     // 896 B, 16B-aligned
    alignas(16) unsigned char Fs[CHUNKS * T];   // 7168 B, 16B-aligned
    alignas(16) unsigned char comp_s[8 * T];
    int sgrp[9];
    int role;
    float fsum;
};

__global__ void __launch_bounds__(256, 4)
k_all(const int* __restrict__ sent, const int* __restrict__ tags,
      const float* __restrict__ emb, const float* __restrict__ W,
      const float* __restrict__ trans, float* __restrict__ out) {
    __shared__ SMem s;
    const int chunk = blockIdx.x, tid = threadIdx.x;
    const int warp = tid >> 5, lane = tid & 31;

    // ===================== Phase 1: feats (4 threads / position) ==============
    for (int i = tid; i < T * EMB; i += 256) s.Ws[i] = W[i];
    __syncthreads();
    const int posL = tid >> 2, q = tid & 3;
    const int pos = chunk * CB + posL;
    const float4* e4 = (const float4*)(emb + (size_t)__ldg(sent + pos) * EMB);
    float acc[T];
#pragma unroll
    for (int t = 0; t < T; t++) acc[t] = 0.0f;
#pragma unroll
    for (int j = 0; j < 19; j++) {
        int k = 4 * j + q;
        if (k < 75) {
            float4 ev = __ldg(e4 + k);
#pragma unroll
            for (int t = 0; t < T; t++) {
                float4 wv = *(const float4*)(s.Ws + t * EMB + 4 * k);
                float a = acc[t];
                a = fmaf(ev.x, wv.x, a); a = fmaf(ev.y, wv.y, a);
                a = fmaf(ev.z, wv.z, a); a = fmaf(ev.w, wv.w, a);
                acc[t] = a;
            }
        }
    }
#pragma unroll
    for (int t = 0; t < T; t++) {
        acc[t] += __shfl_xor_sync(0xFFFFFFFFu, acc[t], 1, 4);
        acc[t] += __shfl_xor_sync(0xFFFFFFFFu, acc[t], 2, 4);
    }
    float4 st;
    st.x = (q==0)?acc[0]:(q==1)?acc[4]:(q==2)?acc[8]:acc[12];
    st.y = (q==0)?acc[1]:(q==1)?acc[5]:(q==2)?acc[9]:acc[13];
    st.z = (q==0)?acc[2]:(q==1)?acc[6]:(q==2)?acc[10]:0.0f;
    st.w = (q==0)?acc[3]:(q==1)?acc[7]:(q==2)?acc[11]:0.0f;
    ((float4*)(s.raw + posL * 16))[q] = st;
    float fm = max14(acc);
    if (q == 0) s.fmaxs[posL] = fm;
    float4 se;
    se.x = __expf(st.x - fm); se.y = __expf(st.y - fm);
    se.z = (q==3) ? 0.0f : __expf(st.z - fm);
    se.w = (q==3) ? 0.0f : __expf(st.w - fm);
    ((float4*)(s.eaux + posL * 16))[q] = se;
    float gv = 0.0f;
    if (q == 0) {
        int tg = __ldg(tags + pos);
        int prev = (pos == 0) ? START_TAG : __ldg(tags + pos - 1);
        float emit = 0.0f;
#pragma unroll
        for (int t = 0; t < T; t++) if (t == tg) emit = acc[t];
        gv = trans[tg * T + prev] + emit;
        if (pos == LSEQ - 1) gv += trans[STOP_TAG * T + tg];
    }
    s.red[tid] = gv;
    if (tid < 196) s.Trs[(tid / 14) * 16 + (tid % 14)] = trans[tid];  // raw
    __syncthreads();
    if (tid < 32) {
        float ff = s.fmaxs[tid] + s.fmaxs[tid + 32];
#pragma unroll
        for (int d = 16; d; d >>= 1) ff += __shfl_xor_sync(0xFFFFFFFFu, ff, d);
        if (tid == 0) s.fsum = ff;
    }
    for (int off = 128; off; off >>= 1) {
        if (tid < off) s.red[tid] += s.red[tid + off];
        __syncthreads();
    }
    if (tid == 0) g_goldpart[chunk] = s.red[0];

    // ===================== Phase 2: viterbi recurrence (warps 0-6) ============
    const int half = lane >> 4, lg = lane & 15;
    const int col = 2 * warp + half;
    const bool ract = (warp < 7) && (lg < 14);
    if (warp < 7) {
        float tr[T]; ld14(&s.Trs[lg * 16], tr);
        if (ract) s.Ucol[0][col * 16 + lg] = (lg == col) ? 0.0f : NINF;
        __syncwarp();
        int b = 0;
        float vfin = 0.0f;
        for (int l = 0; l < CB; l++) {
            float u[T]; ld14(&s.Ucol[b][col * 16], u);
            float a[T];
#pragma unroll
            for (int p = 0; p < T; p++) a[p] = u[p] + tr[p];
            vfin = max14(a) + s.raw[l * 16 + lg];
            if (ract) s.Ucol[b ^ 1][col * 16 + lg] = vfin;
            __syncwarp(); b ^= 1;
        }
        if (ract) g_Cv[chunk * 224 + lg * 16 + col] = vfin;
    }
    __threadfence(); __syncthreads();
    if (tid == 0) atomicAdd(&g_cntc[chunk >> 4], 1);

    // restage exp(trans)
    if (tid < 196) s.Trs[(tid / 14) * 16 + (tid % 14)] = __expf(trans[tid]);
    __syncthreads();

    // ===================== Phase 3: forward recurrence (warps 0-6) ============
    float ffin = 0.0f, ofs = 0.0f;
    if (warp < 7) {
        float tre[T]; ld14(&s.Trs[lg * 16], tre);
        if (ract) s.Ucol[0][col * 16 + lg] = (lg == col) ? 1.0f : 0.0f;
        __syncwarp();
        int b = 0;
        for (int l4 = 0; l4 < CB; l4 += 4) {
            {   // normalization step
                float u[T]; ld14(&s.Ucol[b][col * 16], u);
                float cm = fmaxf(max14(u), 1e-35f);
                float inv = __fdividef(1.0f, cm);
                ofs += __logf(cm);
                float s0 = 0.0f, s1 = 0.0f;
#pragma unroll
                for (int p = 0; p < 7; p++) s0 = fmaf(tre[p], u[p], s0);
#pragma unroll
                for (int p = 7; p < T; p++) s1 = fmaf(tre[p], u[p], s1);
                ffin = (s0 + s1) * inv * s.eaux[l4 * 16 + lg];
                if (ract) s.Ucol[b ^ 1][col * 16 + lg] = ffin;
                __syncwarp(); b ^= 1;
            }
#pragma unroll
            for (int ll = 1; ll < 4; ll++) {
                float u[T]; ld14(&s.Ucol[b][col * 16], u);
                float s0 = 0.0f, s1 = 0.0f;
#pragma unroll
                for (int p = 0; p < 7; p++) s0 = fmaf(tre[p], u[p], s0);
#pragma unroll
                for (int p = 7; p < T; p++) s1 = fmaf(tre[p], u[p], s1);
                ffin = (s0 + s1) * s.eaux[(l4 + ll) * 16 + lg];
                if (ract) s.Ucol[b ^ 1][col * 16 + lg] = ffin;
                __syncwarp(); b ^= 1;
            }
        }
    }
    float Cf = NINF;
    if (ract) {
        Cf = (ffin > 0.0f) ? __logf(ffin) + ofs + s.fsum : NINF;
        s.Msm[lg * 16 + col] = Cf;
    }
    __syncthreads();
    if (ract) {
        float r[T]; ld14(&s.Msm[lg * 16], r);
        float rm = max14(r);
        g_Em[chunk * 224 + lg * 16 + col] = __expf(Cf - rm);
        if (col == 0) g_m[chunk * 16 + lg] = rm;
    }
    __threadfence(); __syncthreads();
    if (tid == 0) atomicAdd(&g_cntc[SUPER + (chunk >> 4)], 1);

    // ===================== Phase 4: super role (chunk 16g+15) =================
    if ((chunk & 15) == 15) {
        int g = chunk >> 4;
        int n = tid % 14, c2 = tid / 14;
        bool act = (tid < 196);
        for (int side = 0; side < 2; side++) {        // 0 = vit, 1 = fwd
            if (tid == 0) {
                while (atomicAdd(&g_cntc[side * SUPER + g], 0) < SCH) __nanosleep(64);
            }
            __syncthreads(); __threadfence();
            if (act) s.Ucol[0][c2 * 16 + n] = side ? ((n == c2) ? 1.0f : 0.0f)
                                                   : ((n == c2) ? 0.0f : NINF);
            float o2 = 0.0f, val2 = 0.0f; int bb = 0;
            __syncthreads();
            for (int k = 0; k < SCH; k++) {
                int ch = g * 16 + k;
                {   const float4* src = (const float4*)(side ? (g_Em + ch * 224)
                                                             : (g_Cv + ch * 224));
                    float4* dst = (float4*)s.Trs;
                    for (int i = tid; i < 56; i += 256) dst[i] = __ldcg(src + i); }
                float mk = (act && side) ? __ldcg(g_m + ch * 16 + n) : 0.0f;
                __syncthreads();
                if (side) {
                    float tlog = 0.0f;
                    if (act) {
                        float u[T], row[T];
                        ld14(&s.Ucol[bb][c2 * 16], u);
                        ld14(&s.Trs[n * 16], row);
                        float s0 = 0.0f, s1 = 0.0f;
#pragma unroll
                        for (int p = 0; p < 7; p++) s0 = fmaf(row[p], u[p], s0);
#pragma unroll
                        for (int p = 7; p < T; p++) s1 = fmaf(row[p], u[p], s1);
                        tlog = mk + __logf(fmaxf(s0 + s1, 1e-38f));
                        s.Msm[c2 * 16 + n] = tlog;
                    }
                    __syncthreads();
                    if (act) {
                        float tc[T]; ld14(&s.Msm[c2 * 16], tc);
                        float cmax = max14(tc);
                        val2 = __expf(tlog - cmax);
                        s.Ucol[bb ^ 1][c2 * 16 + n] = val2;
                        o2 += cmax;
                    }
                    __syncthreads();
                } else {
                    if (act) {
                        float u[T], row[T];
                        ld14(&s.Ucol[bb][c2 * 16], u);
                        ld14(&s.Trs[n * 16], row);
                        float a[T];
#pragma unroll
                        for (int p = 0; p < T; p++) a[p] = row[p] + u[p];
                        val2 = max14(a);
                        s.Ucol[bb ^ 1][c2 * 16 + n] = val2;
                    }
                    __syncthreads();
                }
                bb ^= 1;
            }
            if (side == 0) {
                if (act) g_SCv[g * 224 + n * 16 + c2] = val2;
            } else {
                float Sl = NINF;
                if (act) {
                    Sl = (val2 > 0.0f) ? __logf(val2) + o2 : NINF;
                    s.Msm[n * 16 + c2] = Sl;
                }
                __syncthreads();
                if (act) {
                    float r[T]; ld14(&s.Msm[n * 16], r);
                    float rm = max14(r);
                    g_SEm[g * 224 + n * 16 + c2] = __expf(Sl - rm);
                    if (c2 == 0) g_Sm[g * 16 + n] = rm;
                }
            }
            __threadfence(); __syncthreads();
            if (tid == 0) atomicAdd(&g_cnts[side], 1);
        }
    }

    // ===================== Phase 5: scan roles (chunk 0 / chunk 1) ============
    if (chunk == 0) {
        if (tid == 0) { while (atomicAdd(&g_cnts[0], 0) < SUPER) __nanosleep(64); }
        __syncthreads(); __threadfence();
        if (tid < 16) {
            const unsigned M16 = 0xFFFFu;
            int ln = tid;
            float v = (ln == START_TAG) ? 0.0f : NEGV;
            float row[T], nrow[T];
            if (ln < T) ld14cg(g_SCv + ln * 16, row);
            else { for (int p = 0; p < T; p++) row[p] = NINF; }
            for (int i = 0; i < SUPER; i++) {
                g_vsuper[i * 16 + ln] = (ln < T) ? v : NEGV;
                if (i + 1 < SUPER) {
                    if (ln < T) ld14cg(g_SCv + (i + 1) * 224 + ln * 16, nrow);
                    else { for (int p = 0; p < T; p++) nrow[p] = NINF; }
                }
                float nv = -3e38f;
#pragma unroll
                for (int p = 0; p < T; p++) {
                    float vp = __shfl_sync(M16, v, p, 16);
                    nv = fmaxf(nv, row[p] + vp);
                }
                v = (ln < T) ? nv : NEGV;
#pragma unroll
                for (int p = 0; p < T; p++) row[p] = nrow[p];
            }
        }
        __threadfence(); __syncthreads();
        if (tid == 0) atomicExch(&g_scanv, 1);
    }
    if (chunk == 1) {
        if (tid == 0) { while (atomicAdd(&g_cnts[1], 0) < SUPER) __nanosleep(64); }
        __syncthreads(); __threadfence();
        if (tid < 16) {
            const unsigned M16 = 0xFFFFu;
            int ln = tid;
            float u = (ln == START_TAG) ? 1.0f : 0.0f;
            float O = 0.0f;
            float row[T], nrow[T], mk, nmk;
            if (ln < T) { ld14cg(g_SEm + ln * 16, row); mk = __ldcg(g_Sm + ln); }
            else { for (int p = 0; p < T; p++) row[p] = 0.0f; mk = -3e38f; }
            for (int i = 0; i < SUPER; i++) {
                if (i + 1 < SUPER) {
                    if (ln < T) { ld14cg(g_SEm + (i + 1) * 224 + ln * 16, nrow);
                                  nmk = __ldcg(g_Sm + (i + 1) * 16 + ln); }
                    else { for (int p = 0; p < T; p++) nrow[p] = 0.0f; nmk = -3e38f; }
                }
                float w = 0.0f;
#pragma unroll
                for (int p = 0; p < T; p++) {
                    float up = __shfl_sync(M16, u, p, 16);
                    w = fmaf(row[p], up, w);
                }
                float t2 = mk + __logf(fmaxf(w, 1e-38f));
                float M = t2;
#pragma unroll
                for (int d = 8; d; d >>= 1) M = fmaxf(M, __shfl_xor_sync(M16, M, d, 16));
                u = __expf(t2 - M);
                O += M;
#pragma unroll
                for (int p = 0; p < T; p++) row[p] = nrow[p];
                mk = nmk;
            }
            float val = (ln < T) ? (((u > 0.0f) ? __logf(u) : NINF) + O +
                                    trans[STOP_TAG * T + ln])
                                 : -3e38f;
            float M2 = val;
#pragma unroll
            for (int d = 8; d; d >>= 1) M2 = fmaxf(M2, __shfl_xor_sync(M16, M2, d, 16));
            float e = __expf(val - M2);
#pragma unroll
            for (int d = 8; d; d >>= 1) e += __shfl_xor_sync(M16, e, d, 16);
            float fwd_score = M2 + __logf(e);
            float gp = 0.0f;
            for (int j = ln; j < CHUNKS; j += 16) gp += __ldcg(g_goldpart + j);
#pragma unroll
            for (int d = 8; d; d >>= 1) gp += __shfl_xor_sync(M16, gp, d, 16);
            if (ln == 0) out[0] = fwd_score - gp;      // nll
        }
    }

    // ===================== Phase 6: bp walk (all blocks) ======================
    if (tid == 0) { while (atomicAdd(&g_scanv, 0) == 0) __nanosleep(128); }
    __syncthreads(); __threadfence();
    if (tid < T) {
        int ln = tid;
        int sup = chunk >> 4;
        float v = g_vsuper[sup * 16 + ln];
        for (int k = (sup << 4); k < chunk; k++) {
            float row[T]; ld14cg(g_Cv + k * 224 + ln * 16, row);
            float fvall[T];
#pragma unroll
            for (int p = 0; p < T; p++) fvall[p] = __shfl_sync(0x3FFFu, v, p);
            float nv = NINF;
#pragma unroll
            for (int p = 0; p < T; p++) nv = fmaxf(nv, row[p] + fvall[p]);
            v = nv;
        }
        float tr[T];
#pragma unroll
        for (int p = 0; p < T; p++) tr[p] = trans[ln * T + p];
        float fv = v;
        for (int l = 0; l < CB; l++) {
            float fvall[T];
#pragma unroll
            for (int p = 0; p < T; p++) fvall[p] = __shfl_sync(0x3FFFu, fv, p);
            float a[T];
#pragma unroll
            for (int p = 0; p < T; p++) a[p] = fvall[p] + tr[p];
            float best; int arg;
            amax14(a, best, arg);
            s.bp_s[l * T + ln] = (unsigned char)arg;
            fv = best + s.raw[l * 16 + ln];
        }
        __syncwarp(0x3FFFu);
        int t = ln;
        for (int l = CB - 1; l >= 0; l--) t = s.bp_s[l * T + t];
        g_F[chunk * T + ln] = (unsigned char)t;
        if (chunk == CHUNKS - 1) {
            s.term_s[ln] = fv + trans[STOP_TAG * T + ln];
            __syncwarp(0x3FFFu);
            if (ln == 0) {
                float a2[T];
#pragma unroll
                for (int p = 0; p < T; p++) a2[p] = s.term_s[p];
                float best; int arg;
                amax14(a2, best, arg);
                g_best_last = arg;
                out[1] = best;                          // path_score
            }
        }
    }
    __threadfence(); __syncthreads();
    if (tid == 0) {
        int old = atomicAdd(&g_cnt_bp, 1);
        s.role = (old == CHUNKS - 1);
    }
    __syncthreads();

    // ===================== Phase 7: carry (last-done block) ===================
    if (s.role) {
        __threadfence();
        {   const int4* src = (const int4*)g_F;
            int4* dst = (int4*)s.Fs;
            for (int i = tid; i < (CHUNKS * T) / 16; i += 256) dst[i] = __ldcg(src + i); }
        __syncthreads();
        if (tid < 8 * T) {
            int g = tid / T, x = tid % T;
            int t = x;
            for (int l = g * 64 + 63; l >= g * 64; l--) t = s.Fs[l * T + t];
            s.comp_s[g * T + x] = (unsigned char)t;
        }
        __syncthreads();
        if (tid == 0) {
            int sgv = g_best_last;
            s.sgrp[8] = sgv;
            for (int g = 7; g >= 0; g--) { sgv = s.comp_s[g * T + sgv]; s.sgrp[g] = sgv; }
        }
        __syncthreads();
        if (tid < 8) {
            int g = tid;
            int t = s.sgrp[g + 1];
            for (int l = g * 64 + 63; l >= g * 64; l--) {
                g_carry[l] = t;
                t = s.Fs[l * T + t];
            }
        }
        __threadfence(); __syncthreads();
        if (tid == 0) atomicExch(&g_flag, 1);
    } else {
        if (tid == 0) { while (atomicAdd(&g_flag, 0) == 0) __nanosleep(128); }
        __syncthreads();
    }
    __threadfence();

    // ===================== Phase 8: path emit + counter resets ================
    if (tid == 0) {
        int cc = g_carry[chunk];
        for (int l = CB - 1; l >= 0; l--) {
            out[2 + chunk * CB + l] = (float)cc;
            cc = s.bp_s[l * T + cc];
        }
        int old = atomicAdd(&g_cnt_done, 1);
        if (old == CHUNKS - 1) {
            for (int i = 0; i < 2 * SUPER; i++) g_cntc[i] = 0;
            g_cnts[0] = 0; g_cnts[1] = 0;
            g_cnt_bp = 0; g_scanv = 0; g_flag = 0;
            __threadfence();
            g_cnt_done = 0;
        }
    }
}

// ---------------- launch -----------------------------------------------------
extern "C" void kernel_launch(void* const* d_in, const int* in_sizes, int n_in,
                              void* d_out, int out_size) {
    const int*   sent  = (const int*)d_in[0];
    const int*   tags  = (const int*)d_in[1];
    const float* emb   = (const float*)d_in[2];
    const float* W     = (const float*)d_in[3];
    const float* trans = (const float*)d_in[4];
    float* out = (float*)d_out;
    (void)in_sizes; (void)n_in; (void)out_size;

    k_all<<<CHUNKS, 256>>>(sent, tags, emb, W, trans, out);
}

// round 9
// speedup vs baseline: 1.3511x; 1.3511x over previous
#include <cuda_runtime.h>

#define LSEQ 32768
#define T 14
#define EMB 300
#define CHUNKS 512
#define CB 64             // chunk length (CHUNKS*CB == LSEQ)
#define SUPER 32          // supernodes per side
#define SCH 16            // chunks per supernode
#define START_TAG 12
#define STOP_TAG 13
#define NEGV (-10000.0f)
#define NINF (-1e30f)

// ---------------- scratch (static device globals; no allocation) -------------
__device__ float g_featsP[LSEQ * 16];          // raw feats padded to 16
__device__ float g_goldpart[1024];
__device__ float g_Em[CHUNKS * 224];           // fwd chunk mats (linear, row-norm)
__device__ float g_m[CHUNKS * 16];             // row log-offsets
__device__ float g_Cv[CHUNKS * 224];           // viterbi chunk mats
__device__ float g_SEm[SUPER * 224];
__device__ float g_Sm[SUPER * 16];
__device__ float g_SCv[SUPER * 224];
__device__ float g_vsuper[SUPER * 16];
__device__ int   g_best_last;
__device__ __align__(16) unsigned char g_F[CHUNKS * T];
__device__ int   g_carry[CHUNKS];
// counters: g_cnt_sup reset by K4; g_cnt_bp/g_flag reset by K1 (next replay)
__device__ int   g_cnt_sup;
__device__ int   g_cnt_bp;
__device__ int   g_flag;

__device__ __forceinline__ void ld14(const float* p, float* u) {
    const float4* q = (const float4*)p;
    float4 a = q[0], b = q[1], c = q[2], d = q[3];
    u[0]=a.x; u[1]=a.y; u[2]=a.z; u[3]=a.w;
    u[4]=b.x; u[5]=b.y; u[6]=b.z; u[7]=b.w;
    u[8]=c.x; u[9]=c.y; u[10]=c.z; u[11]=c.w;
    u[12]=d.x; u[13]=d.y;
}
__device__ __forceinline__ float max14(const float* u) {
    float a0=fmaxf(u[0],u[1]), a1=fmaxf(u[2],u[3]), a2=fmaxf(u[4],u[5]);
    float a3=fmaxf(u[6],u[7]), a4=fmaxf(u[8],u[9]), a5=fmaxf(u[10],u[11]);
    float a6=fmaxf(u[12],u[13]);
    float b0=fmaxf(a0,a1), b1=fmaxf(a2,a3), b2=fmaxf(a4,a5);
    return fmaxf(fmaxf(b0,b1), fmaxf(b2,a6));
}
// first-max argmax (ties -> lowest index)
__device__ __forceinline__ void amax14(const float* a, float& best, int& arg) {
    float v[7]; int ix[7];
#pragma unroll
    for (int p = 0; p < 7; p++) {
        bool t = a[2*p] >= a[2*p+1];
        v[p] = t ? a[2*p] : a[2*p+1];
        ix[p] = t ? 2*p : 2*p+1;
    }
    bool t0 = v[0] >= v[1]; float w0 = t0?v[0]:v[1]; int j0 = t0?ix[0]:ix[1];
    bool t1 = v[2] >= v[3]; float w1 = t1?v[2]:v[3]; int j1 = t1?ix[2]:ix[3];
    bool t2 = v[4] >= v[5]; float w2 = t2?v[4]:v[5]; int j2 = t2?ix[4]:ix[5];
    bool s0 = w0 >= w1; float x0 = s0?w0:w1; int y0 = s0?j0:j1;
    bool s1 = w2 >= v[6]; float x1 = s1?w2:v[6]; int y1 = s1?j2:ix[6];
    bool s2 = x0 >= x1; best = s2?x0:x1; arg = s2?y0:y1;
}

// ================= K1: feats + gold (1024 blocks x 128 thr, 32 pos/blk) ======
__global__ void __launch_bounds__(128) k_feats(
        const int* __restrict__ sent, const int* __restrict__ tags,
        const float* __restrict__ emb, const float* __restrict__ W,
        const float* __restrict__ trans) {
    __shared__ __align__(16) float Ws[T * EMB];
    __shared__ float red[128];
    int bid = blockIdx.x, tid = threadIdx.x;
    if (bid == 0 && tid == 0) { g_cnt_bp = 0; g_flag = 0; }   // resets for K4
    {   const float4* src = (const float4*)W;
        float4* dst = (float4*)Ws;
        for (int i = tid; i < (T * EMB) / 4; i += 128) dst[i] = src[i]; }
    __syncthreads();
    int posL = tid >> 2, q = tid & 3;
    int pos = bid * 32 + posL;
    const float4* e4 = (const float4*)(emb + (size_t)__ldg(sent + pos) * EMB);
    float acc[T];
#pragma unroll
    for (int t = 0; t < T; t++) acc[t] = 0.0f;
#pragma unroll
    for (int j = 0; j < 19; j++) {
        int k = 4 * j + q;
        if (k < 75) {
            float4 ev = __ldg(e4 + k);
#pragma unroll
            for (int t = 0; t < T; t++) {
                float4 wv = *(const float4*)(Ws + t * EMB + 4 * k);
                float a = acc[t];
                a = fmaf(ev.x, wv.x, a); a = fmaf(ev.y, wv.y, a);
                a = fmaf(ev.z, wv.z, a); a = fmaf(ev.w, wv.w, a);
                acc[t] = a;
            }
        }
    }
#pragma unroll
    for (int t = 0; t < T; t++) {
        acc[t] += __shfl_xor_sync(0xFFFFFFFFu, acc[t], 1, 4);
        acc[t] += __shfl_xor_sync(0xFFFFFFFFu, acc[t], 2, 4);
    }
    float4 st;
    st.x = (q==0)?acc[0]:(q==1)?acc[4]:(q==2)?acc[8]:acc[12];
    st.y = (q==0)?acc[1]:(q==1)?acc[5]:(q==2)?acc[9]:acc[13];
    st.z = (q==0)?acc[2]:(q==1)?acc[6]:(q==2)?acc[10]:0.0f;
    st.w = (q==0)?acc[3]:(q==1)?acc[7]:(q==2)?acc[11]:0.0f;
    ((float4*)(g_featsP + pos * 16))[q] = st;
    float gv = 0.0f;
    if (q == 0) {
        int tg = __ldg(tags + pos);
        int prev = (pos == 0) ? START_TAG : __ldg(tags + pos - 1);
        float emit = 0.0f;
#pragma unroll
        for (int t = 0; t < T; t++) if (t == tg) emit = acc[t];
        gv = trans[tg * T + prev] + emit;
        if (pos == LSEQ - 1) gv += trans[STOP_TAG * T + tg];
    }
    red[tid] = gv;
    __syncthreads();
    for (int off = 64; off; off >>= 1) {
        if (tid < off) red[tid] += red[tid + off];
        __syncthreads();
    }
    if (tid == 0) g_goldpart[bid] = red[0];
}

// ================= K2: chunk recurrences (1024 blocks x 224 thr) =============
// bid < 512: viterbi (max-plus);  bid >= 512: forward (linear domain)
__global__ void __launch_bounds__(224, 6) k_chunks(const float* __restrict__ trans) {
    __shared__ struct {
        alignas(16) float aux[CB * 16];     // raw feats, then (fwd) exp(feat-fmax)
        alignas(16) float U[2][256];
        alignas(16) float Trs[256];
        alignas(16) float Msm[256];
        alignas(16) float fmaxs[CB];
        float fsum;
    } s;
    int bid = blockIdx.x, tid = threadIdx.x;
    int fwd = (bid >= CHUNKS);
    int chunk = fwd ? bid - CHUNKS : bid;
    {   const float4* src = (const float4*)(g_featsP + chunk * CB * 16);
        float4* dst = (float4*)s.aux;
        for (int i = tid; i < CB * 4; i += 224) dst[i] = src[i]; }
    if (tid < 196) s.Trs[(tid / 14) * 16 + (tid % 14)] =
        fwd ? __expf(trans[tid]) : trans[tid];
    __syncthreads();
    if (fwd) {
        if (tid < CB) {
            float f[T]; ld14(s.aux + tid * 16, f);
            float fm = max14(f);
            s.fmaxs[tid] = fm;
#pragma unroll
            for (int j = 0; j < T; j++) s.aux[tid * 16 + j] = __expf(f[j] - fm);
        }
        __syncthreads();
        if (tid < 32) {
            float ff = s.fmaxs[tid] + s.fmaxs[tid + 32];
#pragma unroll
            for (int d = 16; d; d >>= 1) ff += __shfl_xor_sync(0xFFFFFFFFu, ff, d);
            if (tid == 0) s.fsum = ff;
        }
        __syncthreads();
    }
    int warp = tid >> 5, lane = tid & 31;
    int col = 2 * warp + (lane >> 4), lg = lane & 15;
    bool ract = (lg < 14);
    float tr[T]; ld14(&s.Trs[lg * 16], tr);
    if (!fwd) {
        if (ract) s.U[0][col * 16 + lg] = (lg == col) ? 0.0f : NINF;
        __syncwarp();
        int b = 0; float vfin = NINF;
        for (int l = 0; l < CB; l++) {
            float u[T]; ld14(&s.U[b][col * 16], u);
            float a[T];
#pragma unroll
            for (int p = 0; p < T; p++) a[p] = u[p] + tr[p];
            vfin = max14(a) + s.aux[l * 16 + lg];
            if (ract) s.U[b ^ 1][col * 16 + lg] = vfin;
            __syncwarp(); b ^= 1;
        }
        if (ract) g_Cv[chunk * 224 + lg * 16 + col] = vfin;
    } else {
        if (ract) s.U[0][col * 16 + lg] = (lg == col) ? 1.0f : 0.0f;
        __syncwarp();
        int b = 0; float ffin = 0.0f, ofs = 0.0f;
        for (int l4 = 0; l4 < CB; l4 += 4) {
            {   float u[T]; ld14(&s.U[b][col * 16], u);
                float cm = fmaxf(max14(u), 1e-35f);
                float inv = __fdividef(1.0f, cm);
                ofs += __logf(cm);
                float s0 = 0.0f, s1 = 0.0f;
#pragma unroll
                for (int p = 0; p < 7; p++) s0 = fmaf(tr[p], u[p], s0);
#pragma unroll
                for (int p = 7; p < T; p++) s1 = fmaf(tr[p], u[p], s1);
                ffin = (s0 + s1) * inv * s.aux[l4 * 16 + lg];
                if (ract) s.U[b ^ 1][col * 16 + lg] = ffin;
                __syncwarp(); b ^= 1;
            }
#pragma unroll
            for (int ll = 1; ll < 4; ll++) {
                float u[T]; ld14(&s.U[b][col * 16], u);
                float s0 = 0.0f, s1 = 0.0f;
#pragma unroll
                for (int p = 0; p < 7; p++) s0 = fmaf(tr[p], u[p], s0);
#pragma unroll
                for (int p = 7; p < T; p++) s1 = fmaf(tr[p], u[p], s1);
                ffin = (s0 + s1) * s.aux[(l4 + ll) * 16 + lg];
                if (ract) s.U[b ^ 1][col * 16 + lg] = ffin;
                __syncwarp(); b ^= 1;
            }
        }
        float Cf = NINF;
        if (ract) {
            Cf = (ffin > 0.0f) ? __logf(ffin) + ofs + s.fsum : NINF;
            s.Msm[lg * 16 + col] = Cf;
        }
        __syncthreads();
        if (ract) {
            float r[T]; ld14(&s.Msm[lg * 16], r);
            float rm = max14(r);
            g_Em[chunk * 224 + lg * 16 + col] = __expf(Cf - rm);
            if (col == 0) g_m[chunk * 16 + lg] = rm;
        }
    }
}

// ================= K3: supers (smem-preloaded) + vit scan ====================
// bid 0-31: vit supers; 32-63: fwd supers; 64: vit scan (spins on g_cnt_sup)
__global__ void __launch_bounds__(224) k_sup(void) {
    struct SupS {
        alignas(16) float A[16 * 224];
        alignas(16) float m[256];
        alignas(16) float U[2][256];
        alignas(16) float Msm[256];
    };
    struct ScanS { alignas(16) float B[32 * 224 + 32]; };
    __shared__ union { SupS s; ScanS sc; } u_;
    int bid = blockIdx.x, tid = threadIdx.x;
    if (bid < 32) {
        // ---- viterbi super ----
        {   const float4* src = (const float4*)(g_Cv + bid * 3584);
            float4* dst = (float4*)u_.s.A;
            for (int i = tid; i < 896; i += 224) dst[i] = src[i]; }
        int n = tid % 14, c = tid / 14;
        u_.s.U[0][c * 16 + n] = (n == c) ? 0.0f : NINF;
        __syncthreads();
        int b = 0; float val = NINF;
        for (int k = 0; k < SCH; k++) {
            float row[T]; ld14(&u_.s.A[k * 224 + n * 16], row);
            float uc[T]; ld14(&u_.s.U[b][c * 16], uc);
            float a[T];
#pragma unroll
            for (int p = 0; p < T; p++) a[p] = row[p] + uc[p];
            val = max14(a);
            u_.s.U[b ^ 1][c * 16 + n] = val;
            __syncthreads(); b ^= 1;
        }
        if (c < 14) g_SCv[bid * 224 + n * 16 + c] = val;
        __threadfence(); __syncthreads();
        if (tid == 0) atomicAdd(&g_cnt_sup, 1);
    } else if (bid < 64) {
        // ---- forward super (log domain, smem-preloaded) ----
        int g = bid - 32;
        {   const float4* src = (const float4*)(g_Em + g * 3584);
            float4* dst = (float4*)u_.s.A;
            for (int i = tid; i < 896; i += 224) dst[i] = src[i]; }
        {   const float4* src = (const float4*)(g_m + g * 256);
            float4* dst = (float4*)u_.s.m;
            for (int i = tid; i < 64; i += 224) dst[i] = src[i]; }
        int n = tid % 14, c = tid / 14;
        u_.s.U[0][c * 16 + n] = (n == c) ? 1.0f : 0.0f;
        __syncthreads();
        int b = 0; float val = 0.0f, o2 = 0.0f;
        for (int k = 0; k < SCH; k++) {
            float row[T]; ld14(&u_.s.A[k * 224 + n * 16], row);
            float uc[T]; ld14(&u_.s.U[b][c * 16], uc);
            float mk = u_.s.m[k * 16 + n];
            float s0 = 0.0f, s1 = 0.0f;
#pragma unroll
            for (int p = 0; p < 7; p++) s0 = fmaf(row[p], uc[p], s0);
#pragma unroll
            for (int p = 7; p < T; p++) s1 = fmaf(row[p], uc[p], s1);
            float tlog = mk + __logf(fmaxf(s0 + s1, 1e-38f));
            u_.s.Msm[c * 16 + n] = tlog;
            __syncthreads();
            float tc[T]; ld14(&u_.s.Msm[c * 16], tc);
            float cmax = max14(tc);
            val = __expf(tlog - cmax);
            u_.s.U[b ^ 1][c * 16 + n] = val;
            o2 += cmax;
            __syncthreads(); b ^= 1;
        }
        float Sl = (val > 0.0f) ? __logf(val) + o2 : NINF;
        u_.s.Msm[n * 16 + c] = Sl;
        __syncthreads();
        if (c < 14) {
            float r[T]; ld14(&u_.s.Msm[n * 16], r);
            float rm = max14(r);
            g_SEm[g * 224 + n * 16 + c] = __expf(Sl - rm);
            if (c == 0) g_Sm[g * 16 + n] = rm;
        }
    } else {
        // ---- vit scan ----
        if (tid == 0) { while (atomicAdd(&g_cnt_sup, 0) < 32) __nanosleep(64); }
        __syncthreads(); __threadfence();
        {   const float4* src = (const float4*)g_SCv;
            float4* dst = (float4*)u_.sc.B;
            for (int i = tid; i < 1792; i += 224) dst[i] = __ldcg(src + i); }
        __syncthreads();
        if (tid < 16) {
            const unsigned M16 = 0xFFFFu;
            int ln = tid;
            float v = (ln == START_TAG) ? 0.0f : NEGV;
            for (int i = 0; i < SUPER; i++) {
                g_vsuper[i * 16 + ln] = (ln < T) ? v : NEGV;
                float row[T]; ld14(&u_.sc.B[i * 224 + ln * 16], row);
                float nv = -3e38f;
#pragma unroll
                for (int p = 0; p < T; p++) {
                    float vp = __shfl_sync(M16, v, p, 16);
                    nv = fmaxf(nv, row[p] + vp);
                }
                v = (ln < T) ? nv : NEGV;
            }
        }
    }
}

// ================= K4: tail (bp+carry+path) + fwd scan block =================
// bid < 512: tail for chunk=bid; bid == 512: fwd scan + nll
__global__ void __launch_bounds__(128) k_tail(const float* __restrict__ trans,
                                              float* __restrict__ out) {
    struct TailS {
        alignas(16) float raw[CB * 16];
        alignas(16) float fix[15 * 224 + 16];
        alignas(16) float vs[16];
        alignas(16) float term[16];
        alignas(16) unsigned char bp[CB * T];
        alignas(16) unsigned char Fs[CHUNKS * T];
        alignas(16) unsigned char comp[8 * T];
        int sgrp[9];
        int role;
    };
    struct FscanS {
        alignas(16) float B[32 * 224 + 32];
        alignas(16) float m[SUPER * 16 + 16];
        alignas(16) float gold[1024];
    };
    __shared__ union { TailS t; FscanS f; } u_;
    int bid = blockIdx.x, tid = threadIdx.x;

    if (bid == 512) {
        // ---- forward scan + nll (off critical path) ----
        if (tid == 0) g_cnt_sup = 0;                 // reset for next replay
        {   const float4* src = (const float4*)g_SEm;
            float4* dst = (float4*)u_.f.B;
            for (int i = tid; i < 1792; i += 128) dst[i] = src[i]; }
        {   const float4* src = (const float4*)g_Sm;
            float4* dst = (float4*)u_.f.m;
            for (int i = tid; i < 128; i += 128) dst[i] = src[i]; }
        {   const float4* src = (const float4*)g_goldpart;
            float4* dst = (float4*)u_.f.gold;
            for (int i = tid; i < 256; i += 128) dst[i] = src[i]; }
        __syncthreads();
        if (tid < 16) {
            const unsigned M16 = 0xFFFFu;
            int ln = tid;
            float u = (ln == START_TAG) ? 1.0f : 0.0f;
            float O = 0.0f;
            for (int i = 0; i < SUPER; i++) {
                float row[T]; float mk;
                if (ln < T) { ld14(&u_.f.B[i * 224 + ln * 16], row);
                              mk = u_.f.m[i * 16 + ln]; }
                else {
#pragma unroll
                    for (int p = 0; p < T; p++) row[p] = 0.0f;
                    mk = -3e38f;
                }
                float w = 0.0f;
#pragma unroll
                for (int p = 0; p < T; p++) {
                    float up = __shfl_sync(M16, u, p, 16);
                    w = fmaf(row[p], up, w);
                }
                float t2 = mk + __logf(fmaxf(w, 1e-38f));
                float M = t2;
#pragma unroll
                for (int d = 8; d; d >>= 1) M = fmaxf(M, __shfl_xor_sync(M16, M, d, 16));
                u = __expf(t2 - M);
                O += M;
            }
            float val = (ln < T) ? (((u > 0.0f) ? __logf(u) : NINF) + O +
                                    trans[STOP_TAG * T + ln])
                                 : -3e38f;
            float M2 = val;
#pragma unroll
            for (int d = 8; d; d >>= 1) M2 = fmaxf(M2, __shfl_xor_sync(M16, M2, d, 16));
            float e = __expf(val - M2);
#pragma unroll
            for (int d = 8; d; d >>= 1) e += __shfl_xor_sync(M16, e, d, 16);
            float fwd_score = M2 + __logf(e);
            float gp = 0.0f;
            for (int j = ln; j < 1024; j += 16) gp += u_.f.gold[j];
#pragma unroll
            for (int d = 8; d; d >>= 1) gp += __shfl_xor_sync(M16, gp, d, 16);
            if (ln == 0) out[0] = fwd_score - gp;    // nll
        }
        return;
    }

    // ---- tail role ----
    int chunk = bid;
    int sup = chunk >> 4, base = sup << 4, r = chunk - base;
    {   const float4* src = (const float4*)(g_featsP + chunk * CB * 16);
        float4* dst = (float4*)u_.t.raw;
        for (int i = tid; i < CB * 4; i += 128) dst[i] = src[i]; }
    if (r > 0) {
        const float4* src = (const float4*)(g_Cv + base * 224);
        float4* dst = (float4*)u_.t.fix;
        for (int i = tid; i < r * 56; i += 128) dst[i] = src[i];
    }
    if (tid < 4) ((float4*)u_.t.vs)[tid & 3] = ((const float4*)(g_vsuper + sup * 16))[tid & 3];
    __syncthreads();
    if (tid < T) {
        int ln = tid;
        float v = u_.t.vs[ln];
        for (int k = 0; k < r; k++) {
            float row[T]; ld14(&u_.t.fix[k * 224 + ln * 16], row);
            float fvall[T];
#pragma unroll
            for (int p = 0; p < T; p++) fvall[p] = __shfl_sync(0x3FFFu, v, p);
            float nv = NINF;
#pragma unroll
            for (int p = 0; p < T; p++) nv = fmaxf(nv, row[p] + fvall[p]);
            v = nv;
        }
        float tr[T];
#pragma unroll
        for (int p = 0; p < T; p++) tr[p] = trans[ln * T + p];
        float fv = v;
        for (int l = 0; l < CB; l++) {
            float fvall[T];
#pragma unroll
            for (int p = 0; p < T; p++) fvall[p] = __shfl_sync(0x3FFFu, fv, p);
            float a[T];
#pragma unroll
            for (int p = 0; p < T; p++) a[p] = fvall[p] + tr[p];
            float best; int arg;
            amax14(a, best, arg);
            u_.t.bp[l * T + ln] = (unsigned char)arg;
            fv = best + u_.t.raw[l * 16 + ln];
        }
        __syncwarp(0x3FFFu);
        int t = ln;
        for (int l = CB - 1; l >= 0; l--) t = u_.t.bp[l * T + t];
        g_F[chunk * T + ln] = (unsigned char)t;
        if (chunk == CHUNKS - 1) {
            u_.t.term[ln] = fv + trans[STOP_TAG * T + ln];
            __syncwarp(0x3FFFu);
            if (ln == 0) {
                float a2[T];
#pragma unroll
                for (int p = 0; p < T; p++) a2[p] = u_.t.term[p];
                float best; int arg;
                amax14(a2, best, arg);
                g_best_last = arg;
                out[1] = best;                       // path_score
            }
        }
    }
    __threadfence(); __syncthreads();
    if (tid == 0) {
        int old = atomicAdd(&g_cnt_bp, 1);
        u_.t.role = (old == CHUNKS - 1);
    }
    __syncthreads();
    if (u_.t.role) {
        __threadfence();
        {   const int4* src = (const int4*)g_F;
            int4* dst = (int4*)u_.t.Fs;
            for (int i = tid; i < (CHUNKS * T) / 16; i += 128) dst[i] = __ldcg(src + i); }
        __syncthreads();
        if (tid < 8 * T) {
            int g = tid / T, x = tid % T;
            int t = x;
            for (int l = g * 64 + 63; l >= g * 64; l--) t = u_.t.Fs[l * T + t];
            u_.t.comp[g * T + x] = (unsigned char)t;
        }
        __syncthreads();
        if (tid == 0) {
            int sgv = g_best_last;
            u_.t.sgrp[8] = sgv;
            for (int g = 7; g >= 0; g--) { sgv = u_.t.comp[g * T + sgv]; u_.t.sgrp[g] = sgv; }
        }
        __syncthreads();
        if (tid < 8) {
            int g = tid;
            int t = u_.t.sgrp[g + 1];
            for (int l = g * 64 + 63; l >= g * 64; l--) {
                g_carry[l] = t;
                t = u_.t.Fs[l * T + t];
            }
        }
        __threadfence(); __syncthreads();
        if (tid == 0) atomicExch(&g_flag, 1);
    } else {
        if (tid == 0) { while (atomicAdd(&g_flag, 0) == 0) __nanosleep(128); }
        __syncthreads();
    }
    __threadfence();
    if (tid == 0) {
        int cc = g_carry[chunk];
        for (int l = CB - 1; l >= 0; l--) {
            out[2 + chunk * CB + l] = (float)cc;
            cc = u_.t.bp[l * T + cc];
        }
    }
}

// ---------------- launch -----------------------------------------------------
extern "C" void kernel_launch(void* const* d_in, const int* in_sizes, int n_in,
                              void* d_out, int out_size) {
    const int*   sent  = (const int*)d_in[0];
    const int*   tags  = (const int*)d_in[1];
    const float* emb   = (const float*)d_in[2];
    const float* W     = (const float*)d_in[3];
    const float* trans = (const float*)d_in[4];
    float* out = (float*)d_out;
    (void)in_sizes; (void)n_in; (void)out_size;

    k_feats<<<1024, 128>>>(sent, tags, emb, W, trans);
    k_chunks<<<2 * CHUNKS, 224>>>(trans);
    k_sup<<<65, 224>>>();
    k_tail<<<CHUNKS + 1, 128>>>(trans, out);
}